// round 4
// baseline (speedup 1.0000x reference)
#include <cuda_runtime.h>
#include <math.h>

#define NJ   14
#define ELEM (NJ * 3)      // 42 floats per batch element per tensor
#define TPB  128
#define ROW  43            // padded smem row (gcd(43,32)=1 -> conflict-free)

__device__ __forceinline__ float fast_sqrt(float x) {
    // x >= 0 finite; one MUFU.RSQ + FMUL instead of IEEE sqrt chain
    return x * rsqrtf(x + 1e-30f);
}

// Eigenvector of symmetric 3x3 A for eigenvalue lam, via cross products of
// rows of (A - lam I), picking the largest-norm pair. Branchless selects.
// Output is unit-norm or ~0 (bounded in all cases).
__device__ __forceinline__ void eigvec3(const float A[3][3], float lam, float v[3]) {
    float d0 = A[0][0] - lam, d1 = A[1][1] - lam, d2 = A[2][2] - lam;
    float a01 = A[0][1], a02 = A[0][2], a12 = A[1][2];
    // rows: r0=(d0,a01,a02) r1=(a01,d1,a12) r2=(a02,a12,d2)
    float c0[3] = { a01 * a12 - d1 * a02,   a02 * a01 - d0 * a12,   d0 * d1 - a01 * a01 };   // r0 x r1
    float c1[3] = { a01 * d2  - a12 * a02,  a02 * a02 - d0 * d2,    d0 * a12 - a01 * a02 };  // r0 x r2
    float c2[3] = { d1 * d2   - a12 * a12,  a12 * a02 - a01 * d2,   a01 * a12 - d1 * a02 };  // r1 x r2
    float n0 = c0[0]*c0[0] + c0[1]*c0[1] + c0[2]*c0[2];
    float n1 = c1[0]*c1[0] + c1[1]*c1[1] + c1[2]*c1[2];
    float n2 = c2[0]*c2[0] + c2[1]*c2[1] + c2[2]*c2[2];
    float bx = c0[0], by = c0[1], bz = c0[2], bn = n0;
    if (n1 > bn) { bx = c1[0]; by = c1[1]; bz = c1[2]; bn = n1; }
    if (n2 > bn) { bx = c2[0]; by = c2[1]; bz = c2[2]; bn = n2; }
    float inv = rsqrtf(bn + 1e-30f);
    v[0] = bx * inv; v[1] = by * inv; v[2] = bz * inv;
}

__global__ void __launch_bounds__(TPB, 5)
pampjpe_kernel(const float* __restrict__ pred,
               const float* __restrict__ gt,
               float* __restrict__ out, int B)
{
    __shared__ float sp[TPB * ROW];
    __shared__ float sg[TPB * ROW];

    const int base = blockIdx.x * TPB;
    const int tid  = threadIdx.x;
    const int valid = min(TPB, B - base);
    const int total = valid * ELEM;

    const float* __restrict__ pbase = pred + (size_t)base * ELEM;
    const float* __restrict__ gbase = gt   + (size_t)base * ELEM;

    if (valid == TPB) {
        const int total4 = (TPB * ELEM) / 4;   // 1344 float4 per tensor
        const float4* __restrict__ p4 = (const float4*)pbase;
        const float4* __restrict__ g4 = (const float4*)gbase;
#pragma unroll 3
        for (int i4 = tid; i4 < total4; i4 += TPB) {
            float4 vp = p4[i4];
            float4 vg = g4[i4];
            int idx = i4 * 4;
            float ap[4] = {vp.x, vp.y, vp.z, vp.w};
            float ag[4] = {vg.x, vg.y, vg.z, vg.w};
#pragma unroll
            for (int c = 0; c < 4; c++) {
                int id = idx + c;
                int e = id / ELEM;
                int k = id - e * ELEM;
                sp[e * ROW + k] = ap[c];
                sg[e * ROW + k] = ag[c];
            }
        }
    } else {
        for (int i = tid; i < total; i += TPB) {
            int e = i / ELEM;
            int k = i - e * ELEM;
            sp[e * ROW + k] = pbase[i];
            sg[e * ROW + k] = gbase[i];
        }
    }
    __syncthreads();

    if (tid >= valid) return;

    const float* P = &sp[tid * ROW];
    const float* G = &sg[tid * ROW];

    // Means
    float mu1[3] = {0.f, 0.f, 0.f};
    float mu2[3] = {0.f, 0.f, 0.f};
#pragma unroll
    for (int j = 0; j < NJ; j++) {
#pragma unroll
        for (int a = 0; a < 3; a++) {
            mu1[a] += P[j * 3 + a];
            mu2[a] += G[j * 3 + a];
        }
    }
    const float invJ = 1.0f / (float)NJ;
#pragma unroll
    for (int a = 0; a < 3; a++) { mu1[a] *= invJ; mu2[a] *= invJ; }

    // Cross-covariance K[a][b] = sum_j x_j[a]*y_j[b]; var1 = sum |x|^2
    float K[3][3] = {{0}};
    float var1 = 0.f;
#pragma unroll
    for (int j = 0; j < NJ; j++) {
        float x[3], y[3];
#pragma unroll
        for (int a = 0; a < 3; a++) {
            x[a] = P[j * 3 + a] - mu1[a];
            y[a] = G[j * 3 + a] - mu2[a];
            var1 += x[a] * x[a];
        }
#pragma unroll
        for (int a = 0; a < 3; a++)
#pragma unroll
            for (int b = 0; b < 3; b++)
                K[a][b] += x[a] * y[b];
    }

    // A = K^T K (symmetric, only 6 unique entries)
    float A[3][3];
#pragma unroll
    for (int i = 0; i < 3; i++)
#pragma unroll
        for (int j = i; j < 3; j++) {
            float acc = 0.f;
#pragma unroll
            for (int k = 0; k < 3; k++) acc += K[k][i] * K[k][j];
            A[i][j] = acc; A[j][i] = acc;
        }

    // ---- Cardano closed-form eigenvalues of A (lam0 >= lam1 >= lam2) ----
    const float third = 1.0f / 3.0f;
    float q  = (A[0][0] + A[1][1] + A[2][2]) * third;
    float p1 = A[0][1]*A[0][1] + A[0][2]*A[0][2] + A[1][2]*A[1][2];
    float e0 = A[0][0] - q, e1 = A[1][1] - q, e2 = A[2][2] - q;
    float p2 = e0*e0 + e1*e1 + e2*e2 + 2.0f * p1;
    float p  = fast_sqrt(p2 * (1.0f / 6.0f));
    float invp = __fdividef(1.0f, p + 1e-30f);
    // det(A - qI)
    float detM = e0 * (e1 * e2 - A[1][2]*A[1][2])
               - A[0][1] * (A[0][1] * e2 - A[1][2] * A[0][2])
               + A[0][2] * (A[0][1] * A[1][2] - e1 * A[0][2]);
    float r = 0.5f * detM * invp * invp * invp;
    r = fminf(fmaxf(r, -1.0f), 1.0f);
    float phi = acosf(r) * third;          // phi in [0, pi/3]
    float cphi = __cosf(phi);
    float sphi = fast_sqrt(fmaxf(1.0f - cphi * cphi, 0.0f));  // sin >= 0 on [0,pi/3]
    float lam0 = q + 2.0f * p * cphi;
    float lam2 = q + 2.0f * p * (-0.5f * cphi - 0.8660254f * sphi);
    float lam1 = 3.0f * q - lam0 - lam2;

    // ---- eigenvectors (right singular vectors of K) ----
    float v0[3], v1[3];
    eigvec3(A, lam0, v0);
    eigvec3(A, lam1, v1);
    // orthogonalize v1 against v0 (insurance for near-degenerate lam0~lam1)
    {
        float d = v0[0]*v1[0] + v0[1]*v1[1] + v0[2]*v1[2];
#pragma unroll
        for (int i = 0; i < 3; i++) v1[i] -= d * v0[i];
        float n = rsqrtf(v1[0]*v1[0] + v1[1]*v1[1] + v1[2]*v1[2] + 1e-30f);
#pragma unroll
        for (int i = 0; i < 3; i++) v1[i] *= n;
    }
    // v2 = v0 x v1 forces det(V)=+1
    float v2[3] = {v0[1]*v1[2] - v0[2]*v1[1],
                   v0[2]*v1[0] - v0[0]*v1[2],
                   v0[0]*v1[1] - v0[1]*v1[0]};

    // u0 = normalize(K v0); u1 = normalize(K v1 - (u0.Kv1)u0); u2 = u0 x u1
    float u0[3], u1[3];
#pragma unroll
    for (int i = 0; i < 3; i++) {
        u0[i] = K[i][0]*v0[0] + K[i][1]*v0[1] + K[i][2]*v0[2];
        u1[i] = K[i][0]*v1[0] + K[i][1]*v1[1] + K[i][2]*v1[2];
    }
    float n0 = rsqrtf(u0[0]*u0[0] + u0[1]*u0[1] + u0[2]*u0[2] + 1e-30f);
#pragma unroll
    for (int i = 0; i < 3; i++) u0[i] *= n0;
    float dot01 = u0[0]*u1[0] + u0[1]*u1[1] + u0[2]*u1[2];
#pragma unroll
    for (int i = 0; i < 3; i++) u1[i] -= dot01 * u0[i];
    float n1 = rsqrtf(u1[0]*u1[0] + u1[1]*u1[1] + u1[2]*u1[2] + 1e-30f);
#pragma unroll
    for (int i = 0; i < 3; i++) u1[i] *= n1;
    float u2[3] = {u0[1]*u1[2] - u0[2]*u1[1],
                   u0[2]*u1[0] - u0[0]*u1[2],
                   u0[0]*u1[1] - u0[1]*u1[0]};

    // R = v0 u0^T + v1 u1^T + v2 u2^T  (optimal proper rotation)
    float R[3][3];
#pragma unroll
    for (int i = 0; i < 3; i++)
#pragma unroll
        for (int j = 0; j < 3; j++)
            R[i][j] = v0[i]*u0[j] + v1[i]*u1[j] + v2[i]*u2[j];

    // scale = trace(R K) / var1  (consistent with the R we actually built)
    float trRK = 0.f;
#pragma unroll
    for (int i = 0; i < 3; i++)
#pragma unroll
        for (int k = 0; k < 3; k++)
            trRK += R[i][k] * K[k][i];
    float scale = __fdividef(trRK, var1 + 1e-30f);

    // Per-joint error, averaged
    float acc = 0.f;
#pragma unroll
    for (int j = 0; j < NJ; j++) {
        float x[3], y[3];
#pragma unroll
        for (int a = 0; a < 3; a++) {
            x[a] = P[j * 3 + a] - mu1[a];
            y[a] = G[j * 3 + a] - mu2[a];
        }
        float d0 = scale * (R[0][0]*x[0] + R[0][1]*x[1] + R[0][2]*x[2]) - y[0];
        float d1 = scale * (R[1][0]*x[0] + R[1][1]*x[1] + R[1][2]*x[2]) - y[1];
        float d2 = scale * (R[2][0]*x[0] + R[2][1]*x[1] + R[2][2]*x[2]) - y[2];
        acc += fast_sqrt(d0*d0 + d1*d1 + d2*d2);
    }
    out[base + tid] = acc * invJ;
}

extern "C" void kernel_launch(void* const* d_in, const int* in_sizes, int n_in,
                              void* d_out, int out_size) {
    const float* pred = (const float*)d_in[0];
    const float* gt   = (const float*)d_in[1];
    float* out = (float*)d_out;
    int B = in_sizes[0] / ELEM;
    int grid = (B + TPB - 1) / TPB;
    pampjpe_kernel<<<grid, TPB>>>(pred, gt, out, B);
}

// round 6
// speedup vs baseline: 1.1633x; 1.1633x over previous
#include <cuda_runtime.h>
#include <math.h>

#define NJ   14
#define ELEM (NJ * 3)      // 42 floats per batch element per tensor
#define TPB  128
#define ROW  43            // padded smem row (gcd(43,32)=1 -> conflict-free)

__device__ __forceinline__ float fast_sqrt(float x) {
    // x >= 0 finite; one MUFU.RSQ + FMUL instead of IEEE sqrt chain
    return x * rsqrtf(x + 1e-30f);
}

// Branchless Jacobi rotation, 2 MUFUs deep, division-free.
// Zeroes A[p][q]; accumulates rotation into V.
__device__ __forceinline__ void jacobi_rot(float A[3][3], float V[3][3], int p, int q) {
    float apq = A[p][q];
    float app = A[p][p], aqq = A[q][q];
    float h = aqq - app;                       // tan(2t) = 2 apq / h, |t| <= pi/4
    float w = rsqrtf(h * h + 4.0f * apq * apq + 1e-38f);   // MUFU 1
    float sgn = copysignf(1.0f, h);
    float cos2t = fminf(fabsf(h) * w, 1.0f);   // cos(2t) >= 0 on chosen branch
    float sin2t = 2.0f * apq * w * sgn;        // carries sign(apq)*sign(h)  [BUGFIX]
    float c2 = 0.5f * (1.0f + cos2t);          // cos^2(t) in [0.5, 1]
    float invc = rsqrtf(c2);                   // MUFU 2 (no eps needed)
    float c = c2 * invc;                       // cos(t)
    float s = 0.5f * sin2t * invc;             // sin(t) = sin(2t)/(2 cos t)
    // apq==0 -> s=0 (identity). h==0 -> 45deg with sign(apq). Bounded always.
    int r = 3 - p - q;
    float arp = A[r][p], arq = A[r][q];
    float narp = c * arp - s * arq;
    float narq = s * arp + c * arq;
    A[r][p] = narp; A[p][r] = narp;
    A[r][q] = narq; A[q][r] = narq;
    float napp = c * c * app - 2.0f * s * c * apq + s * s * aqq;
    float naqq = s * s * app + 2.0f * s * c * apq + c * c * aqq;
    A[p][p] = napp; A[q][q] = naqq;
    A[p][q] = 0.0f; A[q][p] = 0.0f;
#pragma unroll
    for (int i = 0; i < 3; i++) {
        float vip = V[i][p], viq = V[i][q];
        V[i][p] = c * vip - s * viq;
        V[i][q] = s * vip + c * viq;
    }
}

__global__ void __launch_bounds__(TPB, 5)
pampjpe_kernel(const float* __restrict__ pred,
               const float* __restrict__ gt,
               float* __restrict__ out, int B)
{
    __shared__ float sp[TPB * ROW];
    __shared__ float sg[TPB * ROW];

    const int base = blockIdx.x * TPB;
    const int tid  = threadIdx.x;
    const int valid = min(TPB, B - base);
    const int total = valid * ELEM;

    const float* __restrict__ pbase = pred + (size_t)base * ELEM;
    const float* __restrict__ gbase = gt   + (size_t)base * ELEM;

    if (valid == TPB) {
        const int total4 = (TPB * ELEM) / 4;   // 1344 float4 per tensor
        const float4* __restrict__ p4 = (const float4*)pbase;
        const float4* __restrict__ g4 = (const float4*)gbase;
#pragma unroll 3
        for (int i4 = tid; i4 < total4; i4 += TPB) {
            float4 vp = p4[i4];
            float4 vg = g4[i4];
            int idx = i4 * 4;
            float ap[4] = {vp.x, vp.y, vp.z, vp.w};
            float ag[4] = {vg.x, vg.y, vg.z, vg.w};
#pragma unroll
            for (int c = 0; c < 4; c++) {
                int id = idx + c;
                int e = id / ELEM;
                int k = id - e * ELEM;
                sp[e * ROW + k] = ap[c];
                sg[e * ROW + k] = ag[c];
            }
        }
    } else {
        for (int i = tid; i < total; i += TPB) {
            int e = i / ELEM;
            int k = i - e * ELEM;
            sp[e * ROW + k] = pbase[i];
            sg[e * ROW + k] = gbase[i];
        }
    }
    __syncthreads();

    if (tid >= valid) return;

    const float* P = &sp[tid * ROW];
    const float* G = &sg[tid * ROW];

    // Means
    float mu1[3] = {0.f, 0.f, 0.f};
    float mu2[3] = {0.f, 0.f, 0.f};
#pragma unroll
    for (int j = 0; j < NJ; j++) {
#pragma unroll
        for (int a = 0; a < 3; a++) {
            mu1[a] += P[j * 3 + a];
            mu2[a] += G[j * 3 + a];
        }
    }
    const float invJ = 1.0f / (float)NJ;
#pragma unroll
    for (int a = 0; a < 3; a++) { mu1[a] *= invJ; mu2[a] *= invJ; }

    // Cross-covariance K[a][b] = sum_j x_j[a]*y_j[b]; var1 = sum |x|^2
    float K[3][3] = {{0}};
    float var1 = 0.f;
#pragma unroll
    for (int j = 0; j < NJ; j++) {
        float x[3], y[3];
#pragma unroll
        for (int a = 0; a < 3; a++) {
            x[a] = P[j * 3 + a] - mu1[a];
            y[a] = G[j * 3 + a] - mu2[a];
            var1 += x[a] * x[a];
        }
#pragma unroll
        for (int a = 0; a < 3; a++)
#pragma unroll
            for (int b = 0; b < 3; b++)
                K[a][b] += x[a] * y[b];
    }

    // A = K^T K (symmetric)
    float A[3][3];
#pragma unroll
    for (int i = 0; i < 3; i++)
#pragma unroll
        for (int j = i; j < 3; j++) {
            float acc = 0.f;
#pragma unroll
            for (int k = 0; k < 3; k++) acc += K[k][i] * K[k][j];
            A[i][j] = acc; A[j][i] = acc;
        }

    // Jacobi eigen-decomposition A = V diag(lam) V^T, 3 cyclic sweeps
    float V[3][3] = {{1.f, 0.f, 0.f}, {0.f, 1.f, 0.f}, {0.f, 0.f, 1.f}};
#pragma unroll
    for (int sweep = 0; sweep < 3; sweep++) {
        jacobi_rot(A, V, 0, 1);
        jacobi_rot(A, V, 0, 2);
        jacobi_rot(A, V, 1, 2);
    }

    float lam[3] = {A[0][0], A[1][1], A[2][2]};
    // Sort eigenpairs descending
#pragma unroll
    for (int a = 0; a < 2; a++)
#pragma unroll
        for (int b = a + 1; b < 3; b++)
            if (lam[a] < lam[b]) {
                float tl = lam[a]; lam[a] = lam[b]; lam[b] = tl;
#pragma unroll
                for (int r = 0; r < 3; r++) {
                    float tv = V[r][a]; V[r][a] = V[r][b]; V[r][b] = tv;
                }
            }

    // v0, v1 = top right singular vectors of K; v2 = v0 x v1 forces det(V)=+1
    float v0[3] = {V[0][0], V[1][0], V[2][0]};
    float v1[3] = {V[0][1], V[1][1], V[2][1]};
    float v2[3] = {v0[1]*v1[2] - v0[2]*v1[1],
                   v0[2]*v1[0] - v0[0]*v1[2],
                   v0[0]*v1[1] - v0[1]*v1[0]};

    // u0 = normalize(K v0); u1 = normalize(K v1 - (u0.Kv1)u0); u2 = u0 x u1
    float u0[3], u1[3];
#pragma unroll
    for (int i = 0; i < 3; i++) {
        u0[i] = K[i][0]*v0[0] + K[i][1]*v0[1] + K[i][2]*v0[2];
        u1[i] = K[i][0]*v1[0] + K[i][1]*v1[1] + K[i][2]*v1[2];
    }
    float n0 = rsqrtf(u0[0]*u0[0] + u0[1]*u0[1] + u0[2]*u0[2] + 1e-30f);
#pragma unroll
    for (int i = 0; i < 3; i++) u0[i] *= n0;
    float dot01 = u0[0]*u1[0] + u0[1]*u1[1] + u0[2]*u1[2];
#pragma unroll
    for (int i = 0; i < 3; i++) u1[i] -= dot01 * u0[i];
    float n1 = rsqrtf(u1[0]*u1[0] + u1[1]*u1[1] + u1[2]*u1[2] + 1e-30f);
#pragma unroll
    for (int i = 0; i < 3; i++) u1[i] *= n1;
    float u2[3] = {u0[1]*u1[2] - u0[2]*u1[1],
                   u0[2]*u1[0] - u0[0]*u1[2],
                   u0[0]*u1[1] - u0[1]*u1[0]};

    // R = v0 u0^T + v1 u1^T + v2 u2^T
    float R[3][3];
#pragma unroll
    for (int i = 0; i < 3; i++)
#pragma unroll
        for (int j = 0; j < 3; j++)
            R[i][j] = v0[i]*u0[j] + v1[i]*u1[j] + v2[i]*u2[j];

    // scale = trace(R K) / var1
    float trRK = 0.f;
#pragma unroll
    for (int i = 0; i < 3; i++)
#pragma unroll
        for (int k = 0; k < 3; k++)
            trRK += R[i][k] * K[k][i];
    float scale = __fdividef(trRK, var1 + 1e-30f);

    // Per-joint error, averaged
    float acc = 0.f;
#pragma unroll
    for (int j = 0; j < NJ; j++) {
        float x[3], y[3];
#pragma unroll
        for (int a = 0; a < 3; a++) {
            x[a] = P[j * 3 + a] - mu1[a];
            y[a] = G[j * 3 + a] - mu2[a];
        }
        float d0 = scale * (R[0][0]*x[0] + R[0][1]*x[1] + R[0][2]*x[2]) - y[0];
        float d1 = scale * (R[1][0]*x[0] + R[1][1]*x[1] + R[1][2]*x[2]) - y[1];
        float d2 = scale * (R[2][0]*x[0] + R[2][1]*x[1] + R[2][2]*x[2]) - y[2];
        acc += fast_sqrt(d0*d0 + d1*d1 + d2*d2);
    }
    out[base + tid] = acc * invJ;
}

extern "C" void kernel_launch(void* const* d_in, const int* in_sizes, int n_in,
                              void* d_out, int out_size) {
    const float* pred = (const float*)d_in[0];
    const float* gt   = (const float*)d_in[1];
    float* out = (float*)d_out;
    int B = in_sizes[0] / ELEM;
    int grid = (B + TPB - 1) / TPB;
    pampjpe_kernel<<<grid, TPB>>>(pred, gt, out, B);
}